// round 15
// baseline (speedup 1.0000x reference)
#include <cuda_runtime.h>
#include <float.h>

#define B_     256
#define D_     1024
#define DG_    4096
#define M_     65536
#define SPK    81
#define TOPK_  32
#define MAXNZ  84
#define EPS_   1e-8f

// ------------------------- device scratch (static) -------------------------
__device__ float          g_expanded[(size_t)B_ * DG_];
__device__ float          g_sims[(size_t)B_ * M_];
__device__ float          g_nzval[MAXNZ * B_];     // [entry][query]
__device__ unsigned short g_nzidx[MAXNZ * B_];
__device__ float          g_invqn[B_];
__device__ int            g_topidx[B_ * TOPK_];

// ---------------------------------------------------------------------------
// K1: expanded = relu(query @ W^T + b)  (256 x 4096, K = 1024, fp32)
// ---------------------------------------------------------------------------
__global__ __launch_bounds__(256) void k_dg_gemm(const float* __restrict__ q,
                                                 const float* __restrict__ W,
                                                 const float* __restrict__ bias)
{
    __shared__ float As[16][129];
    __shared__ float Ws[16][65];
    const int tid = threadIdx.x;
    const int tx = tid & 15, ty = tid >> 4;
    const int m0 = blockIdx.y * 128, n0 = blockIdx.x * 64;

    float c[8][4];
#pragma unroll
    for (int i = 0; i < 8; i++)
#pragma unroll
        for (int j = 0; j < 4; j++) c[i][j] = 0.f;

    for (int k0 = 0; k0 < D_; k0 += 16) {
#pragma unroll 8
        for (int i = tid; i < 128 * 16; i += 256) {
            int k = i & 15, m = i >> 4;
            As[k][m] = q[(size_t)(m0 + m) * D_ + k0 + k];
        }
#pragma unroll 4
        for (int i = tid; i < 64 * 16; i += 256) {
            int k = i & 15, n = i >> 4;
            Ws[k][n] = W[(size_t)(n0 + n) * D_ + k0 + k];
        }
        __syncthreads();
#pragma unroll
        for (int kk = 0; kk < 16; kk++) {
            float a[8], w[4];
#pragma unroll
            for (int i = 0; i < 8; i++) a[i] = As[kk][ty * 8 + i];
#pragma unroll
            for (int j = 0; j < 4; j++) w[j] = Ws[kk][tx * 4 + j];
#pragma unroll
            for (int i = 0; i < 8; i++)
#pragma unroll
                for (int j = 0; j < 4; j++) c[i][j] = fmaf(a[i], w[j], c[i][j]);
        }
        __syncthreads();
    }
#pragma unroll
    for (int i = 0; i < 8; i++) {
        int m = m0 + ty * 8 + i;
#pragma unroll
        for (int j = 0; j < 4; j++) {
            int n = n0 + tx * 4 + j;
            float v = c[i][j] + bias[n];
            g_expanded[(size_t)m * DG_ + n] = v > 0.f ? v : 0.f;
        }
    }
}

// ---------------------------------------------------------------------------
// K2: exact 81st-largest per query (radix select on float bits; all >= 0),
// deterministic compaction to [entry][query] table, zero-padded to MAXNZ,
// plus 1/||sq||. One block per query.
// ---------------------------------------------------------------------------
__global__ __launch_bounds__(256) void k_select()
{
    __shared__ int   scount;
    __shared__ int   soff[257];
    __shared__ float swss[8];
    const int b = blockIdx.x, t = threadIdx.x;
    const float* row = g_expanded + (size_t)b * DG_;

    unsigned bits[16];
#pragma unroll
    for (int i = 0; i < 16; i++) bits[i] = __float_as_uint(row[t + (i << 8)]);

    unsigned prefix = 0;
    int need = SPK;
    for (int bit = 31; bit >= 0; --bit) {
        if (t == 0) scount = 0;
        __syncthreads();
        unsigned hv = (prefix | (1u << bit)) >> bit;
        int lc = 0;
#pragma unroll
        for (int i = 0; i < 16; i++) lc += ((bits[i] >> bit) == hv);
        if (lc) atomicAdd(&scount, lc);
        __syncthreads();
        int c = scount;
        if (c >= need) prefix |= (1u << bit);
        else           need -= c;
        __syncthreads();
    }
    // prefix = bit pattern of the exact 81st largest value
    int lc = 0;
#pragma unroll
    for (int i = 0; i < 16; i++) lc += (bits[i] >= prefix && bits[i] != 0u);
    soff[t] = lc;
    __syncthreads();
    if (t == 0) {
        int run = 0;
        for (int i = 0; i < 256; i++) { int x = soff[i]; soff[i] = run; run += x; }
        soff[256] = run;
    }
    __syncthreads();
    int pos = soff[t];
    float ss = 0.f;
#pragma unroll
    for (int i = 0; i < 16; i++) {
        unsigned bb = bits[i];
        if (bb >= prefix && bb != 0u) {
            float v = __uint_as_float(bb);
            ss = fmaf(v, v, ss);
            if (pos < MAXNZ) {
                g_nzval[pos * B_ + b] = v;
                g_nzidx[pos * B_ + b] = (unsigned short)(t + (i << 8));
            }
            pos++;
        }
    }
    int cnt = soff[256]; if (cnt > MAXNZ) cnt = MAXNZ;
    for (int j = cnt + t; j < MAXNZ; j += 256) {   // zero padding
        g_nzval[j * B_ + b] = 0.f;
        g_nzidx[j * B_ + b] = 0;
    }
#pragma unroll
    for (int o = 16; o; o >>= 1) ss += __shfl_down_sync(0xffffffffu, ss, o);
    if ((t & 31) == 0) swss[t >> 5] = ss;
    __syncthreads();
    if (t == 0) {
        float tot = 0.f;
        for (int w = 0; w < 8; w++) tot += swss[w];
        g_invqn[b] = 1.0f / fmaxf(sqrtf(tot), EPS_);
    }
}

// ---------------------------------------------------------------------------
// K3: sims[b][m] = sparse_dot(sq_b, key_m) * invqn_b * imp_m / max(||key_m||,eps)
// 4 key rows per group interleaved as float4 in smem (one LDS.128 serves 4
// rows); full 256-query sparse table resident in smem; fused key norms.
// ---------------------------------------------------------------------------
__global__ __launch_bounds__(256, 1) void k_sims(const float* __restrict__ keys,
                                                 const float* __restrict__ imp)
{
    extern __shared__ __align__(16) unsigned char sm[];
    float4*         s4     = (float4*)sm;                          // 65536 B
    float*          snzval = (float*)(sm + 65536);                 // 86016 B
    unsigned short* snzidx = (unsigned short*)(sm + 65536 + 86016);// 43008 B
    float*          sred   = (float*)(sm + 65536 + 86016 + 43008); // 32 f
    float*          sscale = sred + 32;                            // 4  f

    const int t = threadIdx.x;
    for (int i = t; i < MAXNZ * B_; i += 256) {
        snzval[i] = g_nzval[i];
        snzidx[i] = g_nzidx[i];
    }
    const float invqn = g_invqn[t];
    __syncthreads();

    const int NG = M_ / 4;
    for (int g = blockIdx.x; g < NG; g += gridDim.x) {
        const int m0 = g * 4;
        const float* k0 = keys + (size_t)(m0 + 0) * DG_;
        const float* k1 = keys + (size_t)(m0 + 1) * DG_;
        const float* k2 = keys + (size_t)(m0 + 2) * DG_;
        const float* k3 = keys + (size_t)(m0 + 3) * DG_;
        float ss0 = 0.f, ss1 = 0.f, ss2 = 0.f, ss3 = 0.f;
#pragma unroll
        for (int i = 0; i < 16; i++) {
            int c = t + (i << 8);
            float v0 = k0[c], v1 = k1[c], v2 = k2[c], v3 = k3[c];
            ss0 = fmaf(v0, v0, ss0); ss1 = fmaf(v1, v1, ss1);
            ss2 = fmaf(v2, v2, ss2); ss3 = fmaf(v3, v3, ss3);
            s4[c] = make_float4(v0, v1, v2, v3);
        }
        // deterministic norm reduction (fixed tree)
#pragma unroll
        for (int o = 16; o; o >>= 1) {
            ss0 += __shfl_down_sync(0xffffffffu, ss0, o);
            ss1 += __shfl_down_sync(0xffffffffu, ss1, o);
            ss2 += __shfl_down_sync(0xffffffffu, ss2, o);
            ss3 += __shfl_down_sync(0xffffffffu, ss3, o);
        }
        if ((t & 31) == 0) {
            int w = t >> 5;
            sred[w] = ss0; sred[8 + w] = ss1; sred[16 + w] = ss2; sred[24 + w] = ss3;
        }
        __syncthreads();
        if (t < 4) {
            float tot = 0.f;
            for (int w = 0; w < 8; w++) tot += sred[t * 8 + w];
            sscale[t] = imp[m0 + t] / fmaxf(sqrtf(tot), EPS_);
        }
        __syncthreads();

        float a0 = 0.f, a1 = 0.f, a2 = 0.f, a3 = 0.f;
#pragma unroll 4
        for (int j = 0; j < MAXNZ; j++) {
            float v  = snzval[j * 256 + t];
            int   ix = snzidx[j * 256 + t];
            float4 kv = s4[ix];
            a0 = fmaf(v, kv.x, a0); a1 = fmaf(v, kv.y, a1);
            a2 = fmaf(v, kv.z, a2); a3 = fmaf(v, kv.w, a3);
        }
        float* srow = g_sims + (size_t)t * M_ + m0;
        srow[0] = a0 * invqn * sscale[0];
        srow[1] = a1 * invqn * sscale[1];
        srow[2] = a2 * invqn * sscale[2];
        srow[3] = a3 * invqn * sscale[3];
        __syncthreads();   // protect s4 / sscale before next group
    }
}

// ---------------------------------------------------------------------------
// K4: exact top-32 per query. Phase 1: per-thread top-32 over 256 coalesced
// elements into conflict-free smem columns. Phase 2: 32 rounds of block
// argmax with (larger val, smaller idx) tie-break. Writes top_sim, topidx,
// and +1.0 usage atomics (fp-exact -> order-independent).
// ---------------------------------------------------------------------------
__global__ __launch_bounds__(256) void k_topk(float* __restrict__ out_sim,
                                              float* __restrict__ out_usage)
{
    extern __shared__ __align__(16) unsigned char sm[];
    float* sv = (float*)sm;                 // [32][256]
    int*   si = (int*)(sm + 32 * 256 * 4);  // [32][256]
    __shared__ float swv[8];
    __shared__ int   swi[8], sws[8];

    const int b = blockIdx.x, t = threadIdx.x;
    const float* srow = g_sims + (size_t)b * M_;

    float cmin = FLT_MAX; int cminpos = 0;
#pragma unroll
    for (int j = 0; j < 32; j++) {
        int m = t + (j << 8);
        float v = srow[m];
        sv[j * 256 + t] = v; si[j * 256 + t] = m;
        if (v < cmin) { cmin = v; cminpos = j; }
    }
    for (int i = 32; i < 256; i++) {
        int m = t + (i << 8);
        float v = srow[m];
        if (v > cmin) {
            sv[cminpos * 256 + t] = v; si[cminpos * 256 + t] = m;
            cmin = FLT_MAX;
#pragma unroll
            for (int j = 0; j < 32; j++) {
                float x = sv[j * 256 + t];
                if (x < cmin) { cmin = x; cminpos = j; }
            }
        }
    }
    __syncthreads();

    for (int r = 0; r < TOPK_; r++) {
        float bv = -FLT_MAX; int bidx = 0x7fffffff, bslot = 0;
#pragma unroll
        for (int j = 0; j < 32; j++) {
            float x = sv[j * 256 + t];
            int  ix = si[j * 256 + t];
            if (x > bv || (x == bv && ix < bidx)) { bv = x; bidx = ix; bslot = j * 256 + t; }
        }
#pragma unroll
        for (int o = 16; o; o >>= 1) {
            float ov = __shfl_down_sync(0xffffffffu, bv, o);
            int  oix = __shfl_down_sync(0xffffffffu, bidx, o);
            int  osl = __shfl_down_sync(0xffffffffu, bslot, o);
            if (ov > bv || (ov == bv && oix < bidx)) { bv = ov; bidx = oix; bslot = osl; }
        }
        if ((t & 31) == 0) { int w = t >> 5; swv[w] = bv; swi[w] = bidx; sws[w] = bslot; }
        __syncthreads();
        if (t == 0) {
            float fv = swv[0]; int fi = swi[0], fs = sws[0];
            for (int w = 1; w < 8; w++) {
                if (swv[w] > fv || (swv[w] == fv && swi[w] < fi)) { fv = swv[w]; fi = swi[w]; fs = sws[w]; }
            }
            out_sim[b * TOPK_ + r] = fv;
            g_topidx[b * TOPK_ + r] = fi;
            atomicAdd(&out_usage[fi], 1.0f);
            sv[fs] = -FLT_MAX;
        }
        __syncthreads();
    }
}

// ---------------------------------------------------------------------------
// K5: retrieved = ca3_values[top_idx]   (one block per (b, rank))
// ---------------------------------------------------------------------------
__global__ __launch_bounds__(256) void k_gather(const float* __restrict__ vals,
                                                float* __restrict__ out_ret)
{
    const int blk = blockIdx.x;
    const int idx = g_topidx[blk];
    const float4* src = (const float4*)(vals + (size_t)idx * D_);
    float4* dst = (float4*)(out_ret + (size_t)blk * D_);
    dst[threadIdx.x] = src[threadIdx.x];
}

__global__ __launch_bounds__(256) void k_copy_usage(const float* __restrict__ uc,
                                                    float* __restrict__ out_usage)
{
    int i = blockIdx.x * 256 + threadIdx.x;
    out_usage[i] = uc[i];
}

// ---------------------------------------------------------------------------
extern "C" void kernel_launch(void* const* d_in, const int* in_sizes, int n_in,
                              void* d_out, int out_size)
{
    const float* query = (const float*)d_in[0];
    const float* dg_W  = (const float*)d_in[1];
    const float* dg_b  = (const float*)d_in[2];
    const float* keys  = (const float*)d_in[3];
    const float* vals  = (const float*)d_in[4];
    const float* imp   = (const float*)d_in[5];
    const float* usage = (const float*)d_in[6];

    float* out_ret   = (float*)d_out;                              // (B, 32, D)
    float* out_sim   = out_ret + (size_t)B_ * TOPK_ * D_;          // (B, 32)
    float* out_usage = out_sim + (size_t)B_ * TOPK_;               // (M,)

    const int SMEM3 = 65536 + 86016 + 43008 + 36 * 4;  // 194,704 B
    const int SMEM4 = 32 * 256 * 8;                    // 65,536 B
    cudaFuncSetAttribute(k_sims, cudaFuncAttributeMaxDynamicSharedMemorySize, SMEM3);
    cudaFuncSetAttribute(k_topk, cudaFuncAttributeMaxDynamicSharedMemorySize, SMEM4);

    k_dg_gemm<<<dim3(DG_ / 64, B_ / 128), 256>>>(query, dg_W, dg_b);
    k_select<<<B_, 256>>>();
    k_sims<<<148, 256, SMEM3>>>(keys, imp);
    k_copy_usage<<<M_ / 256, 256>>>(usage, out_usage);
    k_topk<<<B_, 256, SMEM4>>>(out_sim, out_usage);
    k_gather<<<B_ * TOPK_, 256>>>(vals, out_ret);
}

// round 16
// speedup vs baseline: 1.2165x; 1.2165x over previous
#include <cuda_runtime.h>
#include <float.h>

#define B_     256
#define D_     1024
#define DG_    4096
#define M_     65536
#define SPK    81
#define TOPK_  32
#define MAXNZ  84
#define EPS_   1e-8f
#define GRP    8          // key rows per K3 group

// ------------------------- device scratch (static) -------------------------
__device__ float          g_expanded[(size_t)B_ * DG_];
__device__ float          g_sims[(size_t)B_ * M_];
__device__ float          g_nzval[MAXNZ * B_];     // [entry][query]
__device__ unsigned short g_nzidx[MAXNZ * B_];
__device__ float          g_invqn[B_];
__device__ int            g_topidx[B_ * TOPK_];

// ---------------------------------------------------------------------------
// K1: expanded = relu(query @ W^T + b)  (256 x 4096, K = 1024, fp32)
// float4 micro-tile smem loads (broadcast LDS.128) -> FMA-bound.
// ---------------------------------------------------------------------------
__global__ __launch_bounds__(256) void k_dg_gemm(const float* __restrict__ q,
                                                 const float* __restrict__ W,
                                                 const float* __restrict__ bias)
{
    __shared__ __align__(16) float As[16][132];   // row stride 528 B (16B-aligned)
    __shared__ __align__(16) float Ws[16][68];    // row stride 272 B (16B-aligned)
    const int tid = threadIdx.x;
    const int tx = tid & 15, ty = tid >> 4;
    const int m0 = blockIdx.y * 128, n0 = blockIdx.x * 64;

    float c[8][4];
#pragma unroll
    for (int i = 0; i < 8; i++)
#pragma unroll
        for (int j = 0; j < 4; j++) c[i][j] = 0.f;

    for (int k0 = 0; k0 < D_; k0 += 16) {
#pragma unroll 8
        for (int i = tid; i < 128 * 16; i += 256) {
            int k = i & 15, m = i >> 4;
            As[k][m] = q[(size_t)(m0 + m) * D_ + k0 + k];
        }
#pragma unroll 4
        for (int i = tid; i < 64 * 16; i += 256) {
            int k = i & 15, n = i >> 4;
            Ws[k][n] = W[(size_t)(n0 + n) * D_ + k0 + k];
        }
        __syncthreads();
#pragma unroll
        for (int kk = 0; kk < 16; kk++) {
            const float4* a4 = (const float4*)&As[kk][ty * 8];
            const float4* w4 = (const float4*)&Ws[kk][tx * 4];
            float4 A0 = a4[0], A1 = a4[1];
            float4 Wv = w4[0];
            float a[8] = {A0.x, A0.y, A0.z, A0.w, A1.x, A1.y, A1.z, A1.w};
            float w[4] = {Wv.x, Wv.y, Wv.z, Wv.w};
#pragma unroll
            for (int i = 0; i < 8; i++)
#pragma unroll
                for (int j = 0; j < 4; j++) c[i][j] = fmaf(a[i], w[j], c[i][j]);
        }
        __syncthreads();
    }
#pragma unroll
    for (int i = 0; i < 8; i++) {
        int m = m0 + ty * 8 + i;
#pragma unroll
        for (int j = 0; j < 4; j++) {
            int n = n0 + tx * 4 + j;
            float v = c[i][j] + bias[n];
            g_expanded[(size_t)m * DG_ + n] = v > 0.f ? v : 0.f;
        }
    }
}

// ---------------------------------------------------------------------------
// K2: exact 81st-largest per query (radix select on float bits; all >= 0),
// deterministic prefix-scan compaction to [entry][query] table (zero-padded),
// plus 1/||sq||. One block per query.
// ---------------------------------------------------------------------------
__global__ __launch_bounds__(256) void k_select()
{
    __shared__ int   scount;
    __shared__ int   soff[257];
    __shared__ float swss[8];
    const int b = blockIdx.x, t = threadIdx.x;
    const float* row = g_expanded + (size_t)b * DG_;

    unsigned bits[16];
#pragma unroll
    for (int i = 0; i < 16; i++) bits[i] = __float_as_uint(row[t + (i << 8)]);

    unsigned prefix = 0;
    int need = SPK;
    for (int bit = 31; bit >= 0; --bit) {
        if (t == 0) scount = 0;
        __syncthreads();
        unsigned hv = (prefix | (1u << bit)) >> bit;
        int lc = 0;
#pragma unroll
        for (int i = 0; i < 16; i++) lc += ((bits[i] >> bit) == hv);
        if (lc) atomicAdd(&scount, lc);
        __syncthreads();
        int c = scount;
        if (c >= need) prefix |= (1u << bit);
        else           need -= c;
        __syncthreads();
    }
    int lc = 0;
#pragma unroll
    for (int i = 0; i < 16; i++) lc += (bits[i] >= prefix && bits[i] != 0u);
    soff[t] = lc;
    __syncthreads();
    if (t == 0) {
        int run = 0;
        for (int i = 0; i < 256; i++) { int x = soff[i]; soff[i] = run; run += x; }
        soff[256] = run;
    }
    __syncthreads();
    int pos = soff[t];
    float ss = 0.f;
#pragma unroll
    for (int i = 0; i < 16; i++) {
        unsigned bb = bits[i];
        if (bb >= prefix && bb != 0u) {
            float v = __uint_as_float(bb);
            ss = fmaf(v, v, ss);
            if (pos < MAXNZ) {
                g_nzval[pos * B_ + b] = v;
                g_nzidx[pos * B_ + b] = (unsigned short)(t + (i << 8));
            }
            pos++;
        }
    }
    int cnt = soff[256]; if (cnt > MAXNZ) cnt = MAXNZ;
    for (int j = cnt + t; j < MAXNZ; j += 256) {
        g_nzval[j * B_ + b] = 0.f;
        g_nzidx[j * B_ + b] = 0;
    }
#pragma unroll
    for (int o = 16; o; o >>= 1) ss += __shfl_down_sync(0xffffffffu, ss, o);
    if ((t & 31) == 0) swss[t >> 5] = ss;
    __syncthreads();
    if (t == 0) {
        float tot = 0.f;
        for (int w = 0; w < 8; w++) tot += swss[w];
        g_invqn[b] = 1.0f / fmaxf(sqrtf(tot), EPS_);
    }
}

// ---------------------------------------------------------------------------
// K3: sims[b][m] = sparse_dot(sq_b, key_m) * invqn_b * imp_m / max(||key_m||,eps)
// 512 threads = 2 per query (42 nz each, table IN REGISTERS).
// 8 key rows/group staged as two row-interleaved float4 tables:
// one LDS.128 serves 4 rows; conflict-free STS.128 staging; fused key norms;
// deterministic fixed-order half-combine via smem.
// ---------------------------------------------------------------------------
#define SMEM3_BYTES (2*65536 + 512*16 + 128*4 + 8*4)   // 139,840 B

__global__ __launch_bounds__(512, 1) void k_sims(const float* __restrict__ keys,
                                                 const float* __restrict__ imp)
{
    extern __shared__ __align__(16) unsigned char sm[];
    float4* s4a    = (float4*)sm;                        // rows 0-3, 64 KB
    float4* s4b    = (float4*)(sm + 65536);              // rows 4-7, 64 KB
    float4* spart  = (float4*)(sm + 131072);             // 512 x 16 B
    float*  sred   = (float*)(sm + 131072 + 8192);       // 16 warps x 8 rows
    float*  sscale = sred + 128;                         // 8

    const int t    = threadIdx.x;
    const int q    = t & 255;
    const int h    = t >> 8;          // which half of the nz list
    const int warp = t >> 5;

    // ---- load this thread's 42-entry slice of the sparse table into regs ----
    unsigned po[21];      // two packed 16-bit byte offsets (idx*16) per reg
    float    vv[42];
#pragma unroll
    for (int j = 0; j < 21; j++) {
        int e0 = h * 42 + 2 * j;
        unsigned i0 = g_nzidx[e0 * B_ + q];
        unsigned i1 = g_nzidx[(e0 + 1) * B_ + q];
        po[j] = (i0 << 4) | (i1 << 20);
        vv[2 * j]     = g_nzval[e0 * B_ + q];
        vv[2 * j + 1] = g_nzval[(e0 + 1) * B_ + q];
    }
    const float invqn = g_invqn[q];

    for (int g = blockIdx.x; g < M_ / GRP; g += gridDim.x) {
        const int m0 = g * GRP;

        // ---- stage 8 rows, interleaved; fuse norm accumulation ----
        float ss[8];
#pragma unroll
        for (int r = 0; r < 8; r++) ss[r] = 0.f;
#pragma unroll
        for (int i = 0; i < DG_ / 512; i++) {
            int c = t + i * 512;
            float v[8];
#pragma unroll
            for (int r = 0; r < 8; r++) {
                v[r] = keys[(size_t)(m0 + r) * DG_ + c];
                ss[r] = fmaf(v[r], v[r], ss[r]);
            }
            s4a[c] = make_float4(v[0], v[1], v[2], v[3]);
            s4b[c] = make_float4(v[4], v[5], v[6], v[7]);
        }
#pragma unroll
        for (int r = 0; r < 8; r++) {
            float x = ss[r];
#pragma unroll
            for (int o = 16; o; o >>= 1) x += __shfl_down_sync(0xffffffffu, x, o);
            if ((t & 31) == 0) sred[warp * 8 + r] = x;
        }
        __syncthreads();                               // B1: s4 + sred ready
        if (t < 8) {
            float tot = 0.f;
            for (int w = 0; w < 16; w++) tot += sred[w * 8 + t];
            sscale[t] = imp[m0 + t] / fmaxf(sqrtf(tot), EPS_);
        }

        // ---- register-table gather: 42 nz x 8 rows ----
        float a[8];
#pragma unroll
        for (int r = 0; r < 8; r++) a[r] = 0.f;
#pragma unroll
        for (int j = 0; j < 21; j++) {
            unsigned p  = po[j];
            unsigned o0 = p & 0xFFF0u;
            unsigned o1 = p >> 16;
            float4 ka = *(const float4*)((const char*)s4a + o0);
            float4 kb = *(const float4*)((const char*)s4b + o0);
            float w0 = vv[2 * j];
            a[0] = fmaf(w0, ka.x, a[0]); a[1] = fmaf(w0, ka.y, a[1]);
            a[2] = fmaf(w0, ka.z, a[2]); a[3] = fmaf(w0, ka.w, a[3]);
            a[4] = fmaf(w0, kb.x, a[4]); a[5] = fmaf(w0, kb.y, a[5]);
            a[6] = fmaf(w0, kb.z, a[6]); a[7] = fmaf(w0, kb.w, a[7]);
            float4 kc = *(const float4*)((const char*)s4a + o1);
            float4 kd = *(const float4*)((const char*)s4b + o1);
            float w1 = vv[2 * j + 1];
            a[0] = fmaf(w1, kc.x, a[0]); a[1] = fmaf(w1, kc.y, a[1]);
            a[2] = fmaf(w1, kc.z, a[2]); a[3] = fmaf(w1, kc.w, a[3]);
            a[4] = fmaf(w1, kd.x, a[4]); a[5] = fmaf(w1, kd.y, a[5]);
            a[6] = fmaf(w1, kd.z, a[6]); a[7] = fmaf(w1, kd.w, a[7]);
        }

        // ---- exchange: I output rows 4h..4h+3; give partner the other half ----
        spart[t] = h ? make_float4(a[0], a[1], a[2], a[3])
                     : make_float4(a[4], a[5], a[6], a[7]);
        __syncthreads();                               // B2: spart + sscale ready
        {
            float4 p2 = spart[t ^ 256];
            int rb = 4 * h;
            float r0 = (a[rb + 0] + p2.x) * invqn * sscale[rb + 0];
            float r1 = (a[rb + 1] + p2.y) * invqn * sscale[rb + 1];
            float r2 = (a[rb + 2] + p2.z) * invqn * sscale[rb + 2];
            float r3 = (a[rb + 3] + p2.w) * invqn * sscale[rb + 3];
            *(float4*)&g_sims[(size_t)q * M_ + m0 + rb] = make_float4(r0, r1, r2, r3);
        }
        // no third barrier needed: next-group writes to s4/sred/spart all occur
        // after every thread has passed B1 of the next iteration.
    }
}

// ---------------------------------------------------------------------------
// K4: exact top-32 per query (per-thread top-32 columns + 32 block-argmax
// rounds, jax tie-break: equal value -> smaller index).
// ---------------------------------------------------------------------------
__global__ __launch_bounds__(256) void k_topk(float* __restrict__ out_sim,
                                              float* __restrict__ out_usage)
{
    extern __shared__ __align__(16) unsigned char sm[];
    float* sv = (float*)sm;                 // [32][256]
    int*   si = (int*)(sm + 32 * 256 * 4);  // [32][256]
    __shared__ float swv[8];
    __shared__ int   swi[8], sws[8];

    const int b = blockIdx.x, t = threadIdx.x;
    const float* srow = g_sims + (size_t)b * M_;

    float cmin = FLT_MAX; int cminpos = 0;
#pragma unroll
    for (int j = 0; j < 32; j++) {
        int m = t + (j << 8);
        float v = srow[m];
        sv[j * 256 + t] = v; si[j * 256 + t] = m;
        if (v < cmin) { cmin = v; cminpos = j; }
    }
    for (int i = 32; i < 256; i++) {
        int m = t + (i << 8);
        float v = srow[m];
        if (v > cmin) {
            sv[cminpos * 256 + t] = v; si[cminpos * 256 + t] = m;
            cmin = FLT_MAX;
#pragma unroll
            for (int j = 0; j < 32; j++) {
                float x = sv[j * 256 + t];
                if (x < cmin) { cmin = x; cminpos = j; }
            }
        }
    }
    __syncthreads();

    for (int r = 0; r < TOPK_; r++) {
        float bv = -FLT_MAX; int bidx = 0x7fffffff, bslot = 0;
#pragma unroll
        for (int j = 0; j < 32; j++) {
            float x = sv[j * 256 + t];
            int  ix = si[j * 256 + t];
            if (x > bv || (x == bv && ix < bidx)) { bv = x; bidx = ix; bslot = j * 256 + t; }
        }
#pragma unroll
        for (int o = 16; o; o >>= 1) {
            float ov = __shfl_down_sync(0xffffffffu, bv, o);
            int  oix = __shfl_down_sync(0xffffffffu, bidx, o);
            int  osl = __shfl_down_sync(0xffffffffu, bslot, o);
            if (ov > bv || (ov == bv && oix < bidx)) { bv = ov; bidx = oix; bslot = osl; }
        }
        if ((t & 31) == 0) { int w = t >> 5; swv[w] = bv; swi[w] = bidx; sws[w] = bslot; }
        __syncthreads();
        if (t == 0) {
            float fv = swv[0]; int fi = swi[0], fs = sws[0];
            for (int w = 1; w < 8; w++) {
                if (swv[w] > fv || (swv[w] == fv && swi[w] < fi)) { fv = swv[w]; fi = swi[w]; fs = sws[w]; }
            }
            out_sim[b * TOPK_ + r] = fv;
            g_topidx[b * TOPK_ + r] = fi;
            atomicAdd(&out_usage[fi], 1.0f);   // exact +1.0 adds: order-independent
            sv[fs] = -FLT_MAX;
        }
        __syncthreads();
    }
}

// ---------------------------------------------------------------------------
// K5: retrieved = ca3_values[top_idx]   (one block per (b, rank))
// ---------------------------------------------------------------------------
__global__ __launch_bounds__(256) void k_gather(const float* __restrict__ vals,
                                                float* __restrict__ out_ret)
{
    const int blk = blockIdx.x;
    const int idx = g_topidx[blk];
    const float4* src = (const float4*)(vals + (size_t)idx * D_);
    float4* dst = (float4*)(out_ret + (size_t)blk * D_);
    dst[threadIdx.x] = src[threadIdx.x];
}

__global__ __launch_bounds__(256) void k_copy_usage(const float* __restrict__ uc,
                                                    float* __restrict__ out_usage,
                                                    int off, int n)
{
    int i = blockIdx.x * 256 + threadIdx.x;
    if (i < n) out_usage[off + i] = uc[off + i];
}

// ---------------------------------------------------------------------------
extern "C" void kernel_launch(void* const* d_in, const int* in_sizes, int n_in,
                              void* d_out, int out_size)
{
    const float* query = (const float*)d_in[0];
    const float* dg_W  = (const float*)d_in[1];
    const float* dg_b  = (const float*)d_in[2];
    const float* keys  = (const float*)d_in[3];
    const float* vals  = (const float*)d_in[4];
    const float* imp   = (const float*)d_in[5];
    const float* usage = (const float*)d_in[6];

    float* out_ret   = (float*)d_out;                              // (B, 32, D)
    float* out_sim   = out_ret + (size_t)B_ * TOPK_ * D_;          // (B, 32)
    float* out_usage = out_sim + (size_t)B_ * TOPK_;               // (M,)

    const int SMEM4 = 32 * 256 * 8;
    cudaFuncSetAttribute(k_sims, cudaFuncAttributeMaxDynamicSharedMemorySize, SMEM3_BYTES);
    cudaFuncSetAttribute(k_topk, cudaFuncAttributeMaxDynamicSharedMemorySize, SMEM4);

    // launches 1..5 (k_sims is #6 so ncu -s 5 -c 1 profiles the hot kernel)
    k_dg_gemm<<<dim3(DG_ / 64, B_ / 128), 256>>>(query, dg_W, dg_b);
    k_select<<<B_, 256>>>();
    const int C0 = 22016, C1 = 22016, C2 = M_ - C0 - C1;
    k_copy_usage<<<(C0 + 255) / 256, 256>>>(usage, out_usage, 0, C0);
    k_copy_usage<<<(C1 + 255) / 256, 256>>>(usage, out_usage, C0, C1);
    k_copy_usage<<<(C2 + 255) / 256, 256>>>(usage, out_usage, C0 + C1, C2);
    k_sims<<<148, 512, SMEM3_BYTES>>>(keys, imp);
    k_topk<<<B_, 256, SMEM4>>>(out_sim, out_usage);
    k_gather<<<B_ * TOPK_, 256>>>(vals, out_ret);
}